// round 13
// baseline (speedup 1.0000x reference)
#include <cuda_runtime.h>
#include <cuda_bf16.h>
#include <math.h>
#include <stdint.h>

#define BB 32
#define TT 2048
#define HH 512
#define UU 32
#define ROWS (BB*TT)   // 65536

typedef unsigned int u32;

__device__ float g_sum[BB * HH];
// delta split: [row][u] bf16, hi + lo residual (4 MB each)
__device__ __align__(16) __nv_bfloat16 g_dhi[(size_t)ROWS * UU];
__device__ __align__(16) __nv_bfloat16 g_dlo[(size_t)ROWS * UU];
// pre-split transposed weights: [tensor][u][k] bf16; 0=Wxh 1=Wxl 2=Wth 3=Wtl
__device__ __align__(16) __nv_bfloat16 g_wb[4][UU * HH];   // 128 KB
// pre-split transposed Wa: [h][u] bf16 (hi, lo)
__device__ __align__(16) __nv_bfloat16 g_wa[2][HH * UU];   // 64 KB

// ---------------- helpers ----------------
__device__ __forceinline__ float fast_tanh(float a) {
    return 1.0f - 2.0f / (__expf(2.0f * a) + 1.0f);
}

// split one float2 (consecutive k) into bf16x2 hi + bf16x2 lo (fragment-ready)
__device__ __forceinline__ void cvt2(float2 f, u32& hi, u32& lo) {
    __nv_bfloat162 h = __float22bfloat162_rn(f);
    const u32 hb = *reinterpret_cast<u32*>(&h);
    const float hx = __uint_as_float(hb << 16);
    const float hy = __uint_as_float(hb & 0xffff0000u);
    __nv_bfloat162 l = __float22bfloat162_rn(make_float2(f.x - hx, f.y - hy));
    hi = hb;
    lo = *reinterpret_cast<u32*>(&l);
}

__device__ __forceinline__ void ldm4(u32* r, u32 addr) {
    asm volatile("ldmatrix.sync.aligned.m8n8.x4.shared.b16 {%0,%1,%2,%3}, [%4];"
                 : "=r"(r[0]), "=r"(r[1]), "=r"(r[2]), "=r"(r[3]) : "r"(addr));
}
__device__ __forceinline__ void mma16816(float* d, const u32* a, const u32* b) {
    asm volatile(
        "mma.sync.aligned.m16n8k16.row.col.f32.bf16.bf16.f32 "
        "{%0,%1,%2,%3}, {%4,%5,%6,%7}, {%8,%9}, {%0,%1,%2,%3};"
        : "+f"(d[0]), "+f"(d[1]), "+f"(d[2]), "+f"(d[3])
        : "r"(a[0]), "r"(a[1]), "r"(a[2]), "r"(a[3]), "r"(b[0]), "r"(b[1]));
}

// W tile swizzle: [rows][64B], 16B slots
__device__ __forceinline__ u32 aoff(int row, int slot) {
    const int key = (row & 3) ^ ((row >> 2) & 1);
    return (u32)(row * 64 + ((slot ^ key) << 4));
}
// scores tile swizzle
__device__ __forceinline__ u32 soff(int r, int slot) {
    return (u32)(r * 64 + ((slot ^ ((r >> 1) & 3)) << 4));
}

// =====================================================================
// K0a/b/c: pre-split weights — three independent launches so that
// k_delta is the 4th launch overall (the one ncu captures).
// =====================================================================
__global__ void k_prep_wx(const float* __restrict__ kx) {
    const int i = blockIdx.x * 256 + threadIdx.x;   // i = k*32 + u
    const int k = i >> 5, u = i & 31;
    const float w = kx[i];
    const __nv_bfloat16 h = __float2bfloat16_rn(w);
    g_wb[0][u * HH + k] = h;
    g_wb[1][u * HH + k] = __float2bfloat16_rn(w - __bfloat162float(h));
}
__global__ void k_prep_wt(const float* __restrict__ kt) {
    const int i = blockIdx.x * 256 + threadIdx.x;
    const int k = i >> 5, u = i & 31;
    const float w = kt[i];
    const __nv_bfloat16 h = __float2bfloat16_rn(w);
    g_wb[2][u * HH + k] = h;
    g_wb[3][u * HH + k] = __float2bfloat16_rn(w - __bfloat162float(h));
}
__global__ void k_prep_wa(const float* __restrict__ ka) {
    const int i = blockIdx.x * 256 + threadIdx.x;   // i = u*512 + h
    const int u = i >> 9, h = i & 511;
    const float w = ka[i];
    const __nv_bfloat16 hb = __float2bfloat16_rn(w);
    g_wa[0][h * UU + u] = hb;
    g_wa[1][h * UU + u] = __float2bfloat16_rn(w - __bfloat162float(hb));
}

// =====================================================================
// K1 (HMMA, A-direct) — unchanged from R12 (k_delta is launch #3 now)
// =====================================================================
#define DW_SMEM 65536   // 4 tensors x 8 chunks x 2KB

__global__ void __launch_bounds__(256, 2)
k_delta(const float* __restrict__ x, const float* __restrict__ t,
        const float* __restrict__ bx, const float* __restrict__ bt,
        const float* __restrict__ lambd)
{
    __shared__ __align__(16) char sW[DW_SMEM];
    const u32 sWa = (u32)__cvta_generic_to_shared(sW);

    const int tid = threadIdx.x;
    const int wid = tid >> 5;
    const int lane = tid & 31;
    const int rowBase = blockIdx.x * 256;
    const int row0 = rowBase + wid * 32;

    if (blockIdx.x < 64) g_sum[blockIdx.x * 256 + tid] = 0.0f;

    float accG[2][4][4], accB[2][4][4];
#pragma unroll
    for (int rg = 0; rg < 2; rg++)
#pragma unroll
        for (int j = 0; j < 4; j++)
#pragma unroll
            for (int q = 0; q < 4; q++) { accG[rg][j][q] = 0.0f; accB[rg][j][q] = 0.0f; }

    const char* xb = (const char*)(x + (size_t)(row0 + (lane >> 2)) * HH + (lane & 3) * 2);
    const char* tb = (const char*)(t + (size_t)(row0 + (lane >> 2)) * HH + (lane & 3) * 2);

    const int bu = ((lane >> 4) & 1) * 8 + (lane & 7);
    const int bc0 = (lane >> 3) & 1;

    for (int half = 0; half < 2; half++) {
        __syncthreads();
#pragma unroll
        for (int p = 0; p < 16; p++) {
            const int j = tid + 256 * p;
            const int sl = j & 3, u = (j >> 2) & 31, c = (j >> 7) & 7, ts = j >> 10;
            *(uint4*)(sW + ts * 16384 + c * 2048 + aoff(u, sl)) =
                *(const uint4*)((const char*)g_wb[ts] + u * 1024 + half * 512 + c * 64 + sl * 16);
        }
        __syncthreads();

        for (int c = 0; c < 8; c++) {
#pragma unroll
            for (int s = 0; s < 2; s++) {
                const u32 kbyte = (u32)((half * 256 + c * 32 + s * 16) * 4);
                const u32 wb0 = aoff(bu, bc0 + 2 * s);
                const u32 wb1 = aoff(bu + 16, bc0 + 2 * s);
                const u32 wtile = sWa + c * 2048;

                u32 bh[8], bl[8];
                ldm4(bh + 0, wtile + 0 * 16384 + wb0);
                ldm4(bh + 4, wtile + 0 * 16384 + wb1);
                ldm4(bl + 0, wtile + 1 * 16384 + wb0);
                ldm4(bl + 4, wtile + 1 * 16384 + wb1);
#pragma unroll
                for (int rg = 0; rg < 2; rg++) {
                    const char* p0 = xb + rg * 32768 + kbyte;
                    float2 f0 = *(const float2*)(p0);
                    float2 f1 = *(const float2*)(p0 + 16384);
                    float2 f2 = *(const float2*)(p0 + 32);
                    float2 f3 = *(const float2*)(p0 + 16384 + 32);
                    u32 ah[4], al[4];
                    cvt2(f0, ah[0], al[0]);
                    cvt2(f1, ah[1], al[1]);
                    cvt2(f2, ah[2], al[2]);
                    cvt2(f3, ah[3], al[3]);
#pragma unroll
                    for (int j = 0; j < 4; j++) {
                        mma16816(accG[rg][j], ah, bh + 2 * j);
                        mma16816(accG[rg][j], ah, bl + 2 * j);
                        mma16816(accG[rg][j], al, bh + 2 * j);
                    }
                }

                ldm4(bh + 0, wtile + 2 * 16384 + wb0);
                ldm4(bh + 4, wtile + 2 * 16384 + wb1);
                ldm4(bl + 0, wtile + 3 * 16384 + wb0);
                ldm4(bl + 4, wtile + 3 * 16384 + wb1);
#pragma unroll
                for (int rg = 0; rg < 2; rg++) {
                    const char* p0 = tb + rg * 32768 + kbyte;
                    float2 f0 = *(const float2*)(p0);
                    float2 f1 = *(const float2*)(p0 + 16384);
                    float2 f2 = *(const float2*)(p0 + 32);
                    float2 f3 = *(const float2*)(p0 + 16384 + 32);
                    u32 ah[4], al[4];
                    cvt2(f0, ah[0], al[0]);
                    cvt2(f1, ah[1], al[1]);
                    cvt2(f2, ah[2], al[2]);
                    cvt2(f3, ah[3], al[3]);
#pragma unroll
                    for (int j = 0; j < 4; j++) {
                        mma16816(accB[rg][j], ah, bh + 2 * j);
                        mma16816(accB[rg][j], ah, bl + 2 * j);
                        mma16816(accB[rg][j], al, bh + 2 * j);
                    }
                }
            }
        }
    }

#pragma unroll
    for (int rg = 0; rg < 2; rg++) {
        const int rowL = row0 + rg * 16 + (lane >> 2);
        const int rowH = rowL + 8;
        const float lamL = __ldg(lambd + (rowL & (TT - 1)));
        const float lamH = __ldg(lambd + (rowH & (TT - 1)));
#pragma unroll
        for (int j = 0; j < 4; j++) {
            const int u0 = j * 8 + (lane & 3) * 2;
            const float bx0 = __ldg(bx + u0), bx1 = __ldg(bx + u0 + 1);
            const float bt0 = __ldg(bt + u0), bt1 = __ldg(bt + u0 + 1);
            float2 oL, oH;
            oL.x = lamL * fast_tanh(accG[rg][j][0] + bx0) + (1.0f - lamL) * fast_tanh(accB[rg][j][0] + bt0);
            oL.y = lamL * fast_tanh(accG[rg][j][1] + bx1) + (1.0f - lamL) * fast_tanh(accB[rg][j][1] + bt1);
            oH.x = lamH * fast_tanh(accG[rg][j][2] + bx0) + (1.0f - lamH) * fast_tanh(accB[rg][j][2] + bt0);
            oH.y = lamH * fast_tanh(accG[rg][j][3] + bx1) + (1.0f - lamH) * fast_tanh(accB[rg][j][3] + bt1);

            __nv_bfloat162 h2 = __float22bfloat162_rn(oL);
            float2 hf = __bfloat1622float2(h2);
            *(__nv_bfloat162*)(g_dhi + (size_t)rowL * UU + u0) = h2;
            *(__nv_bfloat162*)(g_dlo + (size_t)rowL * UU + u0) =
                __float22bfloat162_rn(make_float2(oL.x - hf.x, oL.y - hf.y));
            h2 = __float22bfloat162_rn(oH);
            hf = __bfloat1622float2(h2);
            *(__nv_bfloat162*)(g_dhi + (size_t)rowH * UU + u0) = h2;
            *(__nv_bfloat162*)(g_dlo + (size_t)rowH * UU + u0) =
                __float22bfloat162_rn(make_float2(oH.x - hf.x, oH.y - hf.y));
        }
    }
}

// =====================================================================
// K2a: sums only — g_sum[b,h] += sum_rows exp(score). 512 thr (as R11).
// =====================================================================
#define K2S_BH 0
#define K2S_BL 32768
#define K2S_AH 65536
#define K2S_AL 69632
#define K2S_SUM 73728
#define K2_SMEM (K2S_SUM + HH*4)   // 75776

__global__ void __launch_bounds__(512, 1)
k_ssum(int dummy) {
    extern __shared__ char smem[];
    const u32 sb = (u32)__cvta_generic_to_shared(smem);
    float* ssum = (float*)(smem + K2S_SUM);

    const int tid = threadIdx.x;
    const int lane = tid & 31;
    const int wid = tid >> 5;
    const int rowBase = blockIdx.x * 64;

    ssum[tid] = 0.0f;

#pragma unroll
    for (int p = 0; p < 4; p++) {
        const int i = tid + 512 * p;
        const int h = i >> 2, sl = i & 3;
        const u32 d = soff(h, sl);
        *(uint4*)(smem + K2S_BH + d) = *(const uint4*)((const char*)g_wa[0] + h * 64 + sl * 16);
        *(uint4*)(smem + K2S_BL + d) = *(const uint4*)((const char*)g_wa[1] + h * 64 + sl * 16);
    }
    {
        const int i = tid & 255;
        const int r = i >> 2, sl = i & 3;
        const u32 d = soff(r, sl);
        const size_t go = (size_t)(rowBase + r) * 64 + sl * 16;
        if (tid < 256)
            *(uint4*)(smem + K2S_AH + d) = *(const uint4*)((const char*)g_dhi + go);
        else
            *(uint4*)(smem + K2S_AL + d) = *(const uint4*)((const char*)g_dlo + go);
    }
    __syncthreads();

    const int g = lane >> 3, l = lane & 7;
    const int rt = wid & 3;
    const int hq = wid >> 2;

    float acc[16][4];
#pragma unroll
    for (int n = 0; n < 16; n++)
#pragma unroll
        for (int q = 0; q < 4; q++) acc[n][q] = 0.0f;

#pragma unroll
    for (int s = 0; s < 2; s++) {
        u32 ah[4], al[4];
        const u32 ao = soff(rt * 16 + (g & 1) * 8 + l, 2 * s + (g >> 1));
        ldm4(ah, sb + K2S_AH + ao);
        ldm4(al, sb + K2S_AL + ao);
#pragma unroll
        for (int nt = 0; nt < 8; nt++) {
            const int h0 = hq * 128 + nt * 16;
            const u32 bo = soff(h0 + (g >> 1) * 8 + l, 2 * s + (g & 1));
            u32 bh[4], bl[4];
            ldm4(bh, sb + K2S_BH + bo);
            ldm4(bl, sb + K2S_BL + bo);
            mma16816(acc[2 * nt],     ah, bh);
            mma16816(acc[2 * nt],     ah, bl);
            mma16816(acc[2 * nt],     al, bh);
            mma16816(acc[2 * nt + 1], ah, bh + 2);
            mma16816(acc[2 * nt + 1], ah, bl + 2);
            mma16816(acc[2 * nt + 1], al, bh + 2);
        }
    }

#pragma unroll
    for (int n8 = 0; n8 < 16; n8++) {
        const int h = hq * 128 + n8 * 8 + (lane & 3) * 2;
        float s0 = __expf(acc[n8][0]) + __expf(acc[n8][2]);
        float s1 = __expf(acc[n8][1]) + __expf(acc[n8][3]);
        s0 += __shfl_xor_sync(0xffffffffu, s0, 4);
        s0 += __shfl_xor_sync(0xffffffffu, s0, 8);
        s0 += __shfl_xor_sync(0xffffffffu, s0, 16);
        s1 += __shfl_xor_sync(0xffffffffu, s1, 4);
        s1 += __shfl_xor_sync(0xffffffffu, s1, 8);
        s1 += __shfl_xor_sync(0xffffffffu, s1, 16);
        if (lane < 4) {
            atomicAdd(&ssum[h], s0);
            atomicAdd(&ssum[h + 1], s1);
        }
    }
    __syncthreads();

    const int b = blockIdx.x >> 5;
    atomicAdd(&g_sum[b * HH + tid], ssum[tid]);
}

// =====================================================================
// K2b: recompute scores, alpha = exp/sum. 256 thr, h-half per blockIdx.y
// -> 2 CTAs/SM (regs 256x~124 = 32k), staging overlaps compute cross-CTA.
// =====================================================================
#define N2_BH 0
#define N2_BL 16384
#define N2_AH 32768
#define N2_AL 36864
#define N2_INV 40960
#define N2_SMEM (N2_INV + 1024)   // 41984

__global__ void __launch_bounds__(256, 2)
k_norm(float* __restrict__ out) {
    extern __shared__ char smem[];
    const u32 sb = (u32)__cvta_generic_to_shared(smem);
    float* sinv = (float*)(smem + N2_INV);

    const int tid = threadIdx.x;
    const int lane = tid & 31;
    const int wid = tid >> 5;
    const int rowBase = blockIdx.x * 64;
    const int hy = blockIdx.y;              // h half: 0 or 1
    const int b = blockIdx.x >> 5;

    sinv[tid] = 1.0f / g_sum[b * HH + hy * 256 + tid];

    // stage B: this CTA's 256-h half of Wa (hi/lo), swizzled
#pragma unroll
    for (int p = 0; p < 4; p++) {
        const int i = tid + 256 * p;        // 0..1023
        const int h = i >> 2, sl = i & 3;   // h local 0..255
        const u32 d = soff(h, sl);
        const char* src = (const char*)g_wa[0] + (hy * 256 + h) * 64 + sl * 16;
        *(uint4*)(smem + N2_BH + d) = *(const uint4*)src;
        *(uint4*)(smem + N2_BL + d) = *(const uint4*)((const char*)g_wa[1] + (hy * 256 + h) * 64 + sl * 16);
    }
    // stage A: 64 rows hi+lo (each thread one hi and one lo)
    {
        const int r = tid >> 2, sl = tid & 3;
        const u32 d = soff(r, sl);
        const size_t go = (size_t)(rowBase + r) * 64 + sl * 16;
        *(uint4*)(smem + N2_AH + d) = *(const uint4*)((const char*)g_dhi + go);
        *(uint4*)(smem + N2_AL + d) = *(const uint4*)((const char*)g_dlo + go);
    }
    __syncthreads();

    const int g = lane >> 3, l = lane & 7;
    const int rt = wid & 3;                 // row tile (16 rows)
    const int hq = wid >> 2;                // local h quarter (128 h): 0 or 1

    float acc[16][4];
#pragma unroll
    for (int n = 0; n < 16; n++)
#pragma unroll
        for (int q = 0; q < 4; q++) acc[n][q] = 0.0f;

#pragma unroll
    for (int s = 0; s < 2; s++) {
        u32 ah[4], al[4];
        const u32 ao = soff(rt * 16 + (g & 1) * 8 + l, 2 * s + (g >> 1));
        ldm4(ah, sb + N2_AH + ao);
        ldm4(al, sb + N2_AL + ao);
#pragma unroll
        for (int nt = 0; nt < 8; nt++) {
            const int h0 = hq * 128 + nt * 16;   // local h
            const u32 bo = soff(h0 + (g >> 1) * 8 + l, 2 * s + (g & 1));
            u32 bh[4], bl[4];
            ldm4(bh, sb + N2_BH + bo);
            ldm4(bl, sb + N2_BL + bo);
            mma16816(acc[2 * nt],     ah, bh);
            mma16816(acc[2 * nt],     ah, bl);
            mma16816(acc[2 * nt],     al, bh);
            mma16816(acc[2 * nt + 1], ah, bh + 2);
            mma16816(acc[2 * nt + 1], ah, bl + 2);
            mma16816(acc[2 * nt + 1], al, bh + 2);
        }
    }

    const int rowL = rowBase + rt * 16 + (lane >> 2);
    float* oL = out + (size_t)rowL * HH + hy * 256;
    float* oH = oL + 8 * HH;
#pragma unroll
    for (int n8 = 0; n8 < 16; n8++) {
        const int h = hq * 128 + n8 * 8 + (lane & 3) * 2;   // local h
        const float2 inv = *(const float2*)(sinv + h);
        *(float2*)(oL + h) = make_float2(__expf(acc[n8][0]) * inv.x,
                                         __expf(acc[n8][1]) * inv.y);
        *(float2*)(oH + h) = make_float2(__expf(acc[n8][2]) * inv.x,
                                         __expf(acc[n8][3]) * inv.y);
    }
}

// =====================================================================
extern "C" void kernel_launch(void* const* d_in, const int* in_sizes, int n_in,
                              void* d_out, int out_size) {
    const float* x     = (const float*)d_in[0];
    const float* t     = (const float*)d_in[1];
    const float* kx    = (const float*)d_in[2];
    const float* kt    = (const float*)d_in[3];
    const float* ka    = (const float*)d_in[4];
    const float* bx    = (const float*)d_in[5];
    const float* bt    = (const float*)d_in[6];
    const float* lambd = (const float*)d_in[7];
    float* out = (float*)d_out;

    cudaFuncSetAttribute(k_ssum, cudaFuncAttributeMaxDynamicSharedMemorySize, K2_SMEM);
    cudaFuncSetAttribute(k_norm, cudaFuncAttributeMaxDynamicSharedMemorySize, N2_SMEM);

    k_prep_wx<<<HH * UU / 256, 256>>>(kx);            // #0
    k_prep_wt<<<HH * UU / 256, 256>>>(kt);            // #1
    k_prep_wa<<<HH * UU / 256, 256>>>(ka);            // #2
    k_delta<<<ROWS / 256, 256>>>(x, t, bx, bt, lambd);// #3  <- ncu capture
    k_ssum<<<ROWS / 64, 512, K2_SMEM>>>(0);           // #4
    k_norm<<<dim3(ROWS / 64, 2), 256, N2_SMEM>>>(out);// #5
}